// round 3
// baseline (speedup 1.0000x reference)
#include <cuda_runtime.h>
#include <cstdint>

// Problem constants
#define BB   16
#define CC   256
#define NHD  8
#define HDM  32
#define LKC  32
#define GBK  16
#define NWIN 64        // tokens per window (8x8)
#define BWIN 1024      // total windows = 16 * 8 * 8
#define MTOK 65536     // BWIN * NWIN
#define NQKV 768

// Scratch (static device allocations are the sanctioned path)
__device__ float g_qkv[(size_t)MTOK * NQKV];   // [65536, 768] window-ordered
__device__ float g_att[(size_t)MTOK * CC];     // [65536, 256] window-ordered

// window-ordered token index -> original token row in x / out
__device__ __forceinline__ int src_row(int wt) {
    int bw = wt >> 6, p = wt & 63;
    int b  = bw >> 6, w = bw & 63;
    int wy = w >> 3, wx = w & 7;
    int py = p >> 3, px = p & 7;
    return (b << 12) + ((wy * 8 + py) << 6) + (wx * 8 + px);
}

// ---------------------------------------------------------------------------
// Tiled SGEMM: C[M, NT] = A[M, 256] * W[256, NT] + bias
// 128x128 block tile, BK=16, 256 threads, 8x8 register tile.
// GATHER: A rows gathered through src_row (window partition)
// SCATTER: C rows scattered through src_row (window reverse)
// ---------------------------------------------------------------------------
template<int NT, bool GATHER, bool SCATTER>
__global__ __launch_bounds__(256)
void gemm_kernel(const float* __restrict__ A, const float* __restrict__ W,
                 const float* __restrict__ bias, float* __restrict__ Cmat)
{
    const int bm = blockIdx.y;
    const int bn = blockIdx.x;

    __shared__ float As[16][132];   // transposed A tile [k][m], padded
    __shared__ float Bs[16][132];   // B tile [k][n], padded
    __shared__ int rowA[128];

    const int tid = threadIdx.x;
    if (tid < 128) {
        int m = bm * 128 + tid;
        rowA[tid] = (GATHER ? src_row(m) : m) * CC;
    }
    __syncthreads();

    const int tx = tid & 15;   // n-tile coord
    const int ty = tid >> 4;   // m-tile coord

    float acc[8][8];
#pragma unroll
    for (int i = 0; i < 8; i++)
#pragma unroll
        for (int j = 0; j < 8; j++) acc[i][j] = 0.f;

    for (int k0 = 0; k0 < CC; k0 += 16) {
        // A tile: 128 rows x 16 k  (512 float4, 2 per thread), store transposed
#pragma unroll
        for (int t = 0; t < 2; t++) {
            int idx = tid + t * 256;
            int r = idx >> 2, c4 = idx & 3;
            float4 v = *(const float4*)(A + rowA[r] + k0 + c4 * 4);
            As[c4 * 4 + 0][r] = v.x;
            As[c4 * 4 + 1][r] = v.y;
            As[c4 * 4 + 2][r] = v.z;
            As[c4 * 4 + 3][r] = v.w;
        }
        // B tile: 16 rows x 128 cols (512 float4, 2 per thread)
#pragma unroll
        for (int t = 0; t < 2; t++) {
            int idx = tid + t * 256;
            int r = idx >> 5, c4 = idx & 31;
            float4 v = *(const float4*)(W + (size_t)(k0 + r) * NT + bn * 128 + c4 * 4);
            *(float4*)&Bs[r][c4 * 4] = v;
        }
        __syncthreads();

#pragma unroll
        for (int kk = 0; kk < 16; kk++) {
            float a[8], b[8];
            *(float4*)&a[0] = *(const float4*)&As[kk][ty * 8];
            *(float4*)&a[4] = *(const float4*)&As[kk][ty * 8 + 4];
            *(float4*)&b[0] = *(const float4*)&Bs[kk][tx * 8];
            *(float4*)&b[4] = *(const float4*)&Bs[kk][tx * 8 + 4];
#pragma unroll
            for (int i = 0; i < 8; i++)
#pragma unroll
                for (int j = 0; j < 8; j++)
                    acc[i][j] += a[i] * b[j];
        }
        __syncthreads();
    }

    // epilogue: bias + (optionally scattered) store
#pragma unroll
    for (int i = 0; i < 8; i++) {
        int m = bm * 128 + ty * 8 + i;
        int crow = SCATTER ? src_row(m) : m;
#pragma unroll
        for (int j = 0; j < 8; j += 4) {
            int n = bn * 128 + tx * 8 + j;
            float4 v;
            v.x = acc[i][j + 0] + bias[n + 0];
            v.y = acc[i][j + 1] + bias[n + 1];
            v.z = acc[i][j + 2] + bias[n + 2];
            v.w = acc[i][j + 3] + bias[n + 3];
            *(float4*)(Cmat + (size_t)crow * NT + n) = v;
        }
    }
}

// ---------------------------------------------------------------------------
// Attention kernel: one block per (window, head). 128 threads.
//   k_c = E_k^T K (32x32), v_c = E_v^T V, append 16 bank rows -> 48 keys
//   scores = Q K_full^T * scale; softmax; out = P V_full
// smem kept < 48KB by aliasing the (kv, E) staging region with the score mat.
// ---------------------------------------------------------------------------
__global__ __launch_bounds__(128)
void attn_kernel(const float* __restrict__ Ek, const float* __restrict__ Ev,
                 const float* __restrict__ kbank, const float* __restrict__ vbank)
{
    const int bw  = blockIdx.x >> 3;
    const int h   = blockIdx.x & 7;
    const int tid = threadIdx.x;

    __shared__ float q[64][33];     // Q tile (padded)
    __shared__ float kf[48][33];    // compressed K + bank (padded)
    __shared__ float vf[48][33];    // compressed V + bank (padded)
    __shared__ float X[4096];       // phase A: kv [64*32] @0, E [64*32] @2048
                                    // phase B: scores [64][49]
    float* kvb = X;
    float* eb  = X + 2048;
    float* sc  = X;                 // pitch 49

    const float* qkvbase = g_qkv + (size_t)(bw * 64) * NQKV + h * HDM;

    // ---- load Q, K-window, E_k, bank rows
    for (int idx = tid; idx < 2048; idx += 128) {
        int p = idx >> 5, d = idx & 31;
        q[p][d]  = qkvbase[p * NQKV + d];
        kvb[idx] = qkvbase[p * NQKV + 256 + d];
        eb[idx]  = Ek[idx];
    }
    for (int idx = tid; idx < 512; idx += 128) {
        int g = idx >> 5, d = idx & 31;
        kf[32 + g][d] = kbank[g * CC + h * HDM + d];
        vf[32 + g][d] = vbank[g * CC + h * HDM + d];
    }
    __syncthreads();

    // ---- k_c[lk][d] = sum_p E_k[p][lk] * K[p][d]   (2x4 tile per thread)
    {
        int lk0 = (tid >> 3) * 2;
        int d0  = (tid & 7) * 4;
        float a00 = 0.f, a01 = 0.f, a02 = 0.f, a03 = 0.f;
        float a10 = 0.f, a11 = 0.f, a12 = 0.f, a13 = 0.f;
#pragma unroll 4
        for (int p = 0; p < 64; p++) {
            float e0 = eb[p * 32 + lk0], e1 = eb[p * 32 + lk0 + 1];
            float b0 = kvb[p * 32 + d0 + 0], b1 = kvb[p * 32 + d0 + 1];
            float b2 = kvb[p * 32 + d0 + 2], b3 = kvb[p * 32 + d0 + 3];
            a00 += e0 * b0; a01 += e0 * b1; a02 += e0 * b2; a03 += e0 * b3;
            a10 += e1 * b0; a11 += e1 * b1; a12 += e1 * b2; a13 += e1 * b3;
        }
        kf[lk0][d0] = a00; kf[lk0][d0 + 1] = a01; kf[lk0][d0 + 2] = a02; kf[lk0][d0 + 3] = a03;
        kf[lk0 + 1][d0] = a10; kf[lk0 + 1][d0 + 1] = a11; kf[lk0 + 1][d0 + 2] = a12; kf[lk0 + 1][d0 + 3] = a13;
    }
    __syncthreads();

    // ---- reload staging with V-window and E_v
    for (int idx = tid; idx < 2048; idx += 128) {
        int p = idx >> 5, d = idx & 31;
        kvb[idx] = qkvbase[p * NQKV + 512 + d];
        eb[idx]  = Ev[idx];
    }
    __syncthreads();

    // ---- v_c
    {
        int lk0 = (tid >> 3) * 2;
        int d0  = (tid & 7) * 4;
        float a00 = 0.f, a01 = 0.f, a02 = 0.f, a03 = 0.f;
        float a10 = 0.f, a11 = 0.f, a12 = 0.f, a13 = 0.f;
#pragma unroll 4
        for (int p = 0; p < 64; p++) {
            float e0 = eb[p * 32 + lk0], e1 = eb[p * 32 + lk0 + 1];
            float b0 = kvb[p * 32 + d0 + 0], b1 = kvb[p * 32 + d0 + 1];
            float b2 = kvb[p * 32 + d0 + 2], b3 = kvb[p * 32 + d0 + 3];
            a00 += e0 * b0; a01 += e0 * b1; a02 += e0 * b2; a03 += e0 * b3;
            a10 += e1 * b0; a11 += e1 * b1; a12 += e1 * b2; a13 += e1 * b3;
        }
        vf[lk0][d0] = a00; vf[lk0][d0 + 1] = a01; vf[lk0][d0 + 2] = a02; vf[lk0][d0 + 3] = a03;
        vf[lk0 + 1][d0] = a10; vf[lk0 + 1][d0 + 1] = a11; vf[lk0 + 1][d0 + 2] = a12; vf[lk0 + 1][d0 + 3] = a13;
    }
    __syncthreads();

    // ---- scores [64][48]: thread tile 4 rows x 6 cols (overwrites X region)
    {
        int r0 = (tid >> 3) * 4;
        int c0 = (tid & 7) * 6;
        float acc[4][6];
#pragma unroll
        for (int i = 0; i < 4; i++)
#pragma unroll
            for (int j = 0; j < 6; j++) acc[i][j] = 0.f;
#pragma unroll 4
        for (int d = 0; d < 32; d++) {
            float a[4], b[6];
#pragma unroll
            for (int i = 0; i < 4; i++) a[i] = q[r0 + i][d];
#pragma unroll
            for (int j = 0; j < 6; j++) b[j] = kf[c0 + j][d];
#pragma unroll
            for (int i = 0; i < 4; i++)
#pragma unroll
                for (int j = 0; j < 6; j++) acc[i][j] += a[i] * b[j];
        }
        const float scale = 0.17677669529663687f;  // 1/sqrt(32)
#pragma unroll
        for (int i = 0; i < 4; i++)
#pragma unroll
            for (int j = 0; j < 6; j++)
                sc[(r0 + i) * 49 + c0 + j] = acc[i][j] * scale;
    }
    __syncthreads();

    // ---- row softmax (one thread per row)
    if (tid < 64) {
        float m = -1e30f;
#pragma unroll
        for (int j = 0; j < 48; j++) m = fmaxf(m, sc[tid * 49 + j]);
        float s = 0.f;
#pragma unroll
        for (int j = 0; j < 48; j++) {
            float e = expf(sc[tid * 49 + j] - m);
            sc[tid * 49 + j] = e;
            s += e;
        }
        float inv = 1.f / s;
#pragma unroll
        for (int j = 0; j < 48; j++) sc[tid * 49 + j] *= inv;
    }
    __syncthreads();

    // ---- out[64][32] = P @ V_full : thread tile 4x4
    {
        int r0 = (tid >> 3) * 4;
        int c0 = (tid & 7) * 4;
        float acc[4][4];
#pragma unroll
        for (int i = 0; i < 4; i++)
#pragma unroll
            for (int j = 0; j < 4; j++) acc[i][j] = 0.f;
#pragma unroll 4
        for (int j = 0; j < 48; j++) {
            float a[4], b[4];
#pragma unroll
            for (int i = 0; i < 4; i++) a[i] = sc[(r0 + i) * 49 + j];
#pragma unroll
            for (int jj = 0; jj < 4; jj++) b[jj] = vf[j][c0 + jj];
#pragma unroll
            for (int i = 0; i < 4; i++)
#pragma unroll
                for (int jj = 0; jj < 4; jj++) acc[i][jj] += a[i] * b[jj];
        }
        float* ob = g_att + (size_t)(bw * 64) * CC + h * HDM;
#pragma unroll
        for (int i = 0; i < 4; i++) {
            float4 v;
            v.x = acc[i][0]; v.y = acc[i][1]; v.z = acc[i][2]; v.w = acc[i][3];
            *(float4*)(ob + (r0 + i) * CC + c0) = v;
        }
    }
}

// ---------------------------------------------------------------------------
extern "C" void kernel_launch(void* const* d_in, const int* in_sizes, int n_in,
                              void* d_out, int out_size)
{
    const float* x      = (const float*)d_in[0];
    const float* W_qkv  = (const float*)d_in[1];
    const float* b_qkv  = (const float*)d_in[2];
    const float* E_k    = (const float*)d_in[3];
    const float* E_v    = (const float*)d_in[4];
    const float* k_bank = (const float*)d_in[5];
    const float* v_bank = (const float*)d_in[6];
    const float* W_proj = (const float*)d_in[7];
    const float* b_proj = (const float*)d_in[8];
    float* out = (float*)d_out;

    float* qkv = nullptr;
    float* att = nullptr;
    cudaGetSymbolAddress((void**)&qkv, g_qkv);
    cudaGetSymbolAddress((void**)&att, g_att);

    // 1) window-gather + QKV GEMM: [65536,256] @ [256,768]
    {
        dim3 grid(NQKV / 128, MTOK / 128);
        gemm_kernel<NQKV, true, false><<<grid, 256>>>(x, W_qkv, b_qkv, qkv);
    }
    // 2) per (window, head) Linformer attention
    {
        attn_kernel<<<BWIN * NHD, 128>>>(E_k, E_v, k_bank, v_bank);
    }
    // 3) proj GEMM + window-reverse scatter: [65536,256] @ [256,256]
    {
        dim3 grid(CC / 128, MTOK / 128);
        gemm_kernel<CC, false, true><<<grid, 256>>>(att, W_proj, b_proj, out);
    }
}

// round 9
// speedup vs baseline: 1.0592x; 1.0592x over previous
#include <cuda_runtime.h>
#include <cstdint>

// Problem constants
#define BB   16
#define CC   256
#define NHD  8
#define HDM  32
#define LKC  32
#define GBK  16
#define NWIN 64        // tokens per window (8x8)
#define BWIN 1024      // total windows = 16 * 8 * 8
#define MTOK 65536     // BWIN * NWIN
#define NQKV 768

typedef unsigned long long u64;

// Scratch
__device__ float g_qkv[(size_t)MTOK * NQKV];   // [65536, 768] window-ordered
__device__ float g_att[(size_t)MTOK * CC];     // [65536, 256] window-ordered

// window-ordered token index -> original token row in x / out
__device__ __forceinline__ int src_row(int wt) {
    int bw = wt >> 6, p = wt & 63;
    int b  = bw >> 6, w = bw & 63;
    int wy = w >> 3, wx = w & 7;
    int py = p >> 3, px = p & 7;
    return (b << 12) + ((wy * 8 + py) << 6) + (wx * 8 + px);
}

// ---- packed f32x2 helpers (sm_103a FFMA2 path) ----
__device__ __forceinline__ void ffma2(u64& d, u64 a, u64 b) {
    asm("fma.rn.f32x2 %0, %1, %2, %0;" : "+l"(d) : "l"(a), "l"(b));
}
__device__ __forceinline__ u64 swap2(u64 v) {
    unsigned lo, hi;
    asm("mov.b64 {%0, %1}, %2;" : "=r"(lo), "=r"(hi) : "l"(v));
    u64 r;
    asm("mov.b64 %0, {%1, %2};" : "=l"(r) : "r"(hi), "r"(lo));
    return r;
}
__device__ __forceinline__ float2 up2(u64 v) {
    float2 r;
    asm("mov.b64 {%0, %1}, %2;" : "=f"(r.x), "=f"(r.y) : "l"(v));
    return r;
}
__device__ __forceinline__ u64 d2u(double d) { return __double_as_longlong(d); }

// ---------------------------------------------------------------------------
// Tiled SGEMM with packed FFMA2: C[M, NT] = A[M, 256] * W[256, NT] + bias
// 128x128 block tile, BK=16, 256 threads, 8x8 per-thread tile computed as
// 4x4 grid of 2x2 packed blocks (pair-swap scheme). Double-buffered smem,
// one __syncthreads per tile.
// ---------------------------------------------------------------------------
template<int NT, bool GATHER, bool SCATTER>
__global__ __launch_bounds__(256, 2)
void gemm_kernel(const float* __restrict__ A, const float* __restrict__ W,
                 const float* __restrict__ bias, float* __restrict__ Cmat)
{
    const int bm = blockIdx.y;
    const int bn = blockIdx.x;

    __shared__ float As[2][16][132];   // transposed A tile [k][m], padded
    __shared__ float Bs[2][16][132];   // B tile [k][n], padded
    __shared__ int rowA[128];

    const int tid = threadIdx.x;
    if (tid < 128) {
        int m = bm * 128 + tid;
        rowA[tid] = (GATHER ? src_row(m) : m) * CC;
    }
    __syncthreads();

    // load assignments
    const int r_a0 = tid >> 2,          c_a0 = (tid & 3) * 4;   // A rows 0..63
    const int r_a1 = (tid + 256) >> 2;                          // A rows 64..127
    const int r_b0 = tid >> 5,          c_b0 = (tid & 31) * 4;  // B k 0..7
    const int r_b1 = r_b0 + 8;                                  // B k 8..15
    const int ra0off = rowA[r_a0];
    const int ra1off = rowA[r_a1];
    const float* Bbase = W + (size_t)bn * 128 + c_b0;

    const int tx = tid & 15;   // n coord
    const int ty = tid >> 4;   // m coord

    u64 accA[4][4], accB[4][4];
#pragma unroll
    for (int i = 0; i < 4; i++)
#pragma unroll
        for (int j = 0; j < 4; j++) { accA[i][j] = 0ull; accB[i][j] = 0ull; }

    float4 av0, av1, bv0, bv1;

    // prologue: tile 0
    av0 = *(const float4*)(A + ra0off + c_a0);
    av1 = *(const float4*)(A + ra1off + c_a0);
    bv0 = *(const float4*)(Bbase + (size_t)r_b0 * NT);
    bv1 = *(const float4*)(Bbase + (size_t)r_b1 * NT);
    {
        As[0][c_a0 + 0][r_a0] = av0.x; As[0][c_a0 + 1][r_a0] = av0.y;
        As[0][c_a0 + 2][r_a0] = av0.z; As[0][c_a0 + 3][r_a0] = av0.w;
        As[0][c_a0 + 0][r_a1] = av1.x; As[0][c_a0 + 1][r_a1] = av1.y;
        As[0][c_a0 + 2][r_a1] = av1.z; As[0][c_a0 + 3][r_a1] = av1.w;
        *(float4*)&Bs[0][r_b0][c_b0] = bv0;
        *(float4*)&Bs[0][r_b1][c_b0] = bv1;
    }
    __syncthreads();

    int cur = 0;
    for (int it = 0; it < 16; it++) {
        // prefetch next tile into registers
        if (it < 15) {
            int k0 = (it + 1) * 16;
            av0 = *(const float4*)(A + ra0off + k0 + c_a0);
            av1 = *(const float4*)(A + ra1off + k0 + c_a0);
            bv0 = *(const float4*)(Bbase + (size_t)(k0 + r_b0) * NT);
            bv1 = *(const float4*)(Bbase + (size_t)(k0 + r_b1) * NT);
        }

        // compute on current buffer
#pragma unroll
        for (int kk = 0; kk < 16; kk++) {
            const float* ar = &As[cur][kk][ty * 8];
            const float* br = &Bs[cur][kk][tx * 8];
            double2 qa0 = *(const double2*)ar;
            double2 qa1 = *(const double2*)(ar + 4);
            double2 qb0 = *(const double2*)br;
            double2 qb1 = *(const double2*)(br + 4);
            u64 pa[4] = { d2u(qa0.x), d2u(qa0.y), d2u(qa1.x), d2u(qa1.y) };
            u64 pb[4] = { d2u(qb0.x), d2u(qb0.y), d2u(qb1.x), d2u(qb1.y) };
            u64 sa[4];
#pragma unroll
            for (int p = 0; p < 4; p++) sa[p] = swap2(pa[p]);
#pragma unroll
            for (int ip = 0; ip < 4; ip++)
#pragma unroll
                for (int jp = 0; jp < 4; jp++) {
                    ffma2(accA[ip][jp], pa[ip], pb[jp]);
                    ffma2(accB[ip][jp], sa[ip], pb[jp]);
                }
        }

        if (it < 15) {
            int nxt = cur ^ 1;
            As[nxt][c_a0 + 0][r_a0] = av0.x; As[nxt][c_a0 + 1][r_a0] = av0.y;
            As[nxt][c_a0 + 2][r_a0] = av0.z; As[nxt][c_a0 + 3][r_a0] = av0.w;
            As[nxt][c_a0 + 0][r_a1] = av1.x; As[nxt][c_a0 + 1][r_a1] = av1.y;
            As[nxt][c_a0 + 2][r_a1] = av1.z; As[nxt][c_a0 + 3][r_a1] = av1.w;
            *(float4*)&Bs[nxt][r_b0][c_b0] = bv0;
            *(float4*)&Bs[nxt][r_b1][c_b0] = bv1;
            __syncthreads();
            cur = nxt;
        }
    }

    // epilogue: unpack 2x2 packed blocks, add bias, store
#pragma unroll
    for (int ip = 0; ip < 4; ip++) {
        int m0 = bm * 128 + ty * 8 + 2 * ip;
        int crow0 = SCATTER ? src_row(m0)     : m0;
        int crow1 = SCATTER ? src_row(m0 + 1) : m0 + 1;
#pragma unroll
        for (int jp = 0; jp < 4; jp++) {
            int c = bn * 128 + tx * 8 + 2 * jp;
            float b0 = bias[c], b1 = bias[c + 1];
            float2 fA = up2(accA[ip][jp]);   // (acc[r0][c], acc[r1][c+1])
            float2 fB = up2(accB[ip][jp]);   // (acc[r1][c], acc[r0][c+1])
            float2 s0 = make_float2(fA.x + b0, fB.y + b1);
            float2 s1 = make_float2(fB.x + b0, fA.y + b1);
            *(float2*)(Cmat + (size_t)crow0 * NT + c) = s0;
            *(float2*)(Cmat + (size_t)crow1 * NT + c) = s1;
        }
    }
}

// ---------------------------------------------------------------------------
// Attention kernel: one block per (window, head). 128 threads.
// ---------------------------------------------------------------------------
__global__ __launch_bounds__(128)
void attn_kernel(const float* __restrict__ Ek, const float* __restrict__ Ev,
                 const float* __restrict__ kbank, const float* __restrict__ vbank)
{
    const int bw  = blockIdx.x >> 3;
    const int h   = blockIdx.x & 7;
    const int tid = threadIdx.x;

    __shared__ float q[64][33];
    __shared__ float kf[48][33];
    __shared__ float vf[48][33];
    __shared__ float X[4096];
    float* kvb = X;
    float* eb  = X + 2048;
    float* sc  = X;                 // pitch 49

    const float* qkvbase = g_qkv + (size_t)(bw * 64) * NQKV + h * HDM;

    for (int idx = tid; idx < 2048; idx += 128) {
        int p = idx >> 5, d = idx & 31;
        q[p][d]  = qkvbase[p * NQKV + d];
        kvb[idx] = qkvbase[p * NQKV + 256 + d];
        eb[idx]  = Ek[idx];
    }
    for (int idx = tid; idx < 512; idx += 128) {
        int g = idx >> 5, d = idx & 31;
        kf[32 + g][d] = kbank[g * CC + h * HDM + d];
        vf[32 + g][d] = vbank[g * CC + h * HDM + d];
    }
    __syncthreads();

    {
        int lk0 = (tid >> 3) * 2;
        int d0  = (tid & 7) * 4;
        float a00 = 0.f, a01 = 0.f, a02 = 0.f, a03 = 0.f;
        float a10 = 0.f, a11 = 0.f, a12 = 0.f, a13 = 0.f;
#pragma unroll 4
        for (int p = 0; p < 64; p++) {
            float e0 = eb[p * 32 + lk0], e1 = eb[p * 32 + lk0 + 1];
            float b0 = kvb[p * 32 + d0 + 0], b1 = kvb[p * 32 + d0 + 1];
            float b2 = kvb[p * 32 + d0 + 2], b3 = kvb[p * 32 + d0 + 3];
            a00 += e0 * b0; a01 += e0 * b1; a02 += e0 * b2; a03 += e0 * b3;
            a10 += e1 * b0; a11 += e1 * b1; a12 += e1 * b2; a13 += e1 * b3;
        }
        kf[lk0][d0] = a00; kf[lk0][d0 + 1] = a01; kf[lk0][d0 + 2] = a02; kf[lk0][d0 + 3] = a03;
        kf[lk0 + 1][d0] = a10; kf[lk0 + 1][d0 + 1] = a11; kf[lk0 + 1][d0 + 2] = a12; kf[lk0 + 1][d0 + 3] = a13;
    }
    __syncthreads();

    for (int idx = tid; idx < 2048; idx += 128) {
        int p = idx >> 5, d = idx & 31;
        kvb[idx] = qkvbase[p * NQKV + 512 + d];
        eb[idx]  = Ev[idx];
    }
    __syncthreads();

    {
        int lk0 = (tid >> 3) * 2;
        int d0  = (tid & 7) * 4;
        float a00 = 0.f, a01 = 0.f, a02 = 0.f, a03 = 0.f;
        float a10 = 0.f, a11 = 0.f, a12 = 0.f, a13 = 0.f;
#pragma unroll 4
        for (int p = 0; p < 64; p++) {
            float e0 = eb[p * 32 + lk0], e1 = eb[p * 32 + lk0 + 1];
            float b0 = kvb[p * 32 + d0 + 0], b1 = kvb[p * 32 + d0 + 1];
            float b2 = kvb[p * 32 + d0 + 2], b3 = kvb[p * 32 + d0 + 3];
            a00 += e0 * b0; a01 += e0 * b1; a02 += e0 * b2; a03 += e0 * b3;
            a10 += e1 * b0; a11 += e1 * b1; a12 += e1 * b2; a13 += e1 * b3;
        }
        vf[lk0][d0] = a00; vf[lk0][d0 + 1] = a01; vf[lk0][d0 + 2] = a02; vf[lk0][d0 + 3] = a03;
        vf[lk0 + 1][d0] = a10; vf[lk0 + 1][d0 + 1] = a11; vf[lk0 + 1][d0 + 2] = a12; vf[lk0 + 1][d0 + 3] = a13;
    }
    __syncthreads();

    {
        int r0 = (tid >> 3) * 4;
        int c0 = (tid & 7) * 6;
        float acc[4][6];
#pragma unroll
        for (int i = 0; i < 4; i++)
#pragma unroll
            for (int j = 0; j < 6; j++) acc[i][j] = 0.f;
#pragma unroll 4
        for (int d = 0; d < 32; d++) {
            float a[4], b[6];
#pragma unroll
            for (int i = 0; i < 4; i++) a[i] = q[r0 + i][d];
#pragma unroll
            for (int j = 0; j < 6; j++) b[j] = kf[c0 + j][d];
#pragma unroll
            for (int i = 0; i < 4; i++)
#pragma unroll
                for (int j = 0; j < 6; j++) acc[i][j] += a[i] * b[j];
        }
        const float scale = 0.17677669529663687f;
#pragma unroll
        for (int i = 0; i < 4; i++)
#pragma unroll
            for (int j = 0; j < 6; j++)
                sc[(r0 + i) * 49 + c0 + j] = acc[i][j] * scale;
    }
    __syncthreads();

    if (tid < 64) {
        float m = -1e30f;
#pragma unroll
        for (int j = 0; j < 48; j++) m = fmaxf(m, sc[tid * 49 + j]);
        float s = 0.f;
#pragma unroll
        for (int j = 0; j < 48; j++) {
            float e = expf(sc[tid * 49 + j] - m);
            sc[tid * 49 + j] = e;
            s += e;
        }
        float inv = 1.f / s;
#pragma unroll
        for (int j = 0; j < 48; j++) sc[tid * 49 + j] *= inv;
    }
    __syncthreads();

    {
        int r0 = (tid >> 3) * 4;
        int c0 = (tid & 7) * 4;
        float acc[4][4];
#pragma unroll
        for (int i = 0; i < 4; i++)
#pragma unroll
            for (int j = 0; j < 4; j++) acc[i][j] = 0.f;
#pragma unroll 4
        for (int j = 0; j < 48; j++) {
            float a[4], b[4];
#pragma unroll
            for (int i = 0; i < 4; i++) a[i] = sc[(r0 + i) * 49 + j];
#pragma unroll
            for (int jj = 0; jj < 4; jj++) b[jj] = vf[j][c0 + jj];
#pragma unroll
            for (int i = 0; i < 4; i++)
#pragma unroll
                for (int jj = 0; jj < 4; jj++) acc[i][jj] += a[i] * b[jj];
        }
        float* ob = g_att + (size_t)(bw * 64) * CC + h * HDM;
#pragma unroll
        for (int i = 0; i < 4; i++) {
            float4 v;
            v.x = acc[i][0]; v.y = acc[i][1]; v.z = acc[i][2]; v.w = acc[i][3];
            *(float4*)(ob + (r0 + i) * CC + c0) = v;
        }
    }
}

// ---------------------------------------------------------------------------
extern "C" void kernel_launch(void* const* d_in, const int* in_sizes, int n_in,
                              void* d_out, int out_size)
{
    const float* x      = (const float*)d_in[0];
    const float* W_qkv  = (const float*)d_in[1];
    const float* b_qkv  = (const float*)d_in[2];
    const float* E_k    = (const float*)d_in[3];
    const float* E_v    = (const float*)d_in[4];
    const float* k_bank = (const float*)d_in[5];
    const float* v_bank = (const float*)d_in[6];
    const float* W_proj = (const float*)d_in[7];
    const float* b_proj = (const float*)d_in[8];
    float* out = (float*)d_out;

    float* qkv = nullptr;
    float* att = nullptr;
    cudaGetSymbolAddress((void**)&qkv, g_qkv);
    cudaGetSymbolAddress((void**)&att, g_att);

    // 1) window-gather + QKV GEMM: [65536,256] @ [256,768]
    {
        dim3 grid(NQKV / 128, MTOK / 128);
        gemm_kernel<NQKV, true, false><<<grid, 256>>>(x, W_qkv, b_qkv, qkv);
    }
    // 2) per (window, head) Linformer attention
    {
        attn_kernel<<<BWIN * NHD, 128>>>(E_k, E_v, k_bank, v_bank);
    }
    // 3) proj GEMM + window-reverse scatter: [65536,256] @ [256,256]
    {
        dim3 grid(CC / 128, MTOK / 128);
        gemm_kernel<CC, false, true><<<grid, 256>>>(att, W_proj, b_proj, out);
    }
}

// round 13
// speedup vs baseline: 1.6300x; 1.5389x over previous
#include <cuda_runtime.h>
#include <cuda_bf16.h>
#include <cstdint>
#include <cstring>

#define CC   256
#define NQKV 768
#define MTOK 65536
#define BWIN 1024
#define NHD  8
#define HDM  32

typedef unsigned long long u64;
typedef unsigned int u32;
typedef __nv_bfloat16 bf16;

// ---------------- scratch ----------------
__device__ float g_qkv[(size_t)MTOK * NQKV];   // window-ordered qkv
__device__ float g_att[(size_t)MTOK * CC];     // window-ordered attn out
__device__ bf16 g_wq0[NQKV * CC];              // W_qkv^T hi  [n][k]
__device__ bf16 g_wq1[NQKV * CC];              // W_qkv^T lo
__device__ bf16 g_wp0[CC * CC];                // W_proj^T hi
__device__ bf16 g_wp1[CC * CC];                // W_proj^T lo

// window-ordered token index -> original token row
__device__ __forceinline__ int src_row(int wt) {
    int bw = wt >> 6, p = wt & 63;
    int b  = bw >> 6, w = bw & 63;
    int wy = w >> 3, wx = w & 7;
    int py = p >> 3, px = p & 7;
    return (b << 12) + ((wy * 8 + py) << 6) + (wx * 8 + px);
}

// ---------------- helpers ----------------
__device__ __forceinline__ u32 cvta_smem(const void* p) {
    u32 a;
    asm("{ .reg .u64 t; cvta.to.shared.u64 t, %1; cvt.u32.u64 %0, t; }" : "=r"(a) : "l"(p));
    return a;
}
__device__ __forceinline__ void sts128(u32 addr, uint4 v) {
    asm volatile("st.shared.v4.b32 [%0], {%1, %2, %3, %4};"
                 :: "r"(addr), "r"(v.x), "r"(v.y), "r"(v.z), "r"(v.w) : "memory");
}
__device__ __forceinline__ void ldsm4(u32& r0, u32& r1, u32& r2, u32& r3, u32 addr) {
    asm volatile("ldmatrix.sync.aligned.m8n8.x4.shared.b16 {%0,%1,%2,%3}, [%4];"
                 : "=r"(r0), "=r"(r1), "=r"(r2), "=r"(r3) : "r"(addr));
}
__device__ __forceinline__ void mma16816(float* d, const u32* a, const u32* b) {
    asm volatile(
        "mma.sync.aligned.m16n8k16.row.col.f32.bf16.bf16.f32 "
        "{%0,%1,%2,%3}, {%4,%5,%6,%7}, {%8,%9}, {%0,%1,%2,%3};"
        : "+f"(d[0]), "+f"(d[1]), "+f"(d[2]), "+f"(d[3])
        : "r"(a[0]), "r"(a[1]), "r"(a[2]), "r"(a[3]), "r"(b[0]), "r"(b[1]));
}
__device__ __forceinline__ u32 bf2u(__nv_bfloat162 h) {
    u32 v; memcpy(&v, &h, 4); return v;
}

// ---------------------------------------------------------------------------
// prep: transpose + hi/lo bf16 split of both weight matrices
// ---------------------------------------------------------------------------
__global__ void prep_w(const float* __restrict__ Wq, const float* __restrict__ Wp) {
    int i = blockIdx.x * 256 + threadIdx.x;
    {
        int n = i >> 8, k = i & 255;
        float f = Wq[k * NQKV + n];
        bf16 h = __float2bfloat16_rn(f);
        g_wq0[i] = h;
        g_wq1[i] = __float2bfloat16_rn(f - __bfloat162float(h));
    }
    if (i < CC * CC) {
        int n = i >> 8, k = i & 255;
        float f = Wp[k * CC + n];
        bf16 h = __float2bfloat16_rn(f);
        g_wp0[i] = h;
        g_wp1[i] = __float2bfloat16_rn(f - __bfloat162float(h));
    }
}

// ---------------------------------------------------------------------------
// HMMA GEMM (mma.sync bf16, 3-product split): C[M,NT] = A[M,256]*W + bias
// 128x128 block tile, BK=32, 8 warps, warp tile 64x32.
// smem per stage (40960 B): A_hi @0, A_lo @10240, B_hi @20480, B_lo @30720
// row pitch 80 B (32 bf16 data + 16 B pad) -> conflict-free ldmatrix.
// ---------------------------------------------------------------------------
template<int NT, bool GATHER, bool SCATTER>
__global__ __launch_bounds__(256, 1)
void gemm_mma(const float* __restrict__ A,
              const bf16* __restrict__ Bt0, const bf16* __restrict__ Bt1,
              const float* __restrict__ bias, float* __restrict__ C)
{
    extern __shared__ __align__(128) char dsm[];
    const u32 sb = cvta_smem(dsm);
    const int tid = threadIdx.x, w = tid >> 5, l = tid & 31;
    const int bn = blockIdx.x, bm = blockIdx.y;

    // ---- load thread coords: row r (0..127), half hh (16 cols each)
    const int r = tid >> 1, hh = tid & 1;
    const float* pa = A + (size_t)(GATHER ? src_row(bm * 128 + r) : (bm * 128 + r)) * CC + hh * 16;
    const bf16* pb0 = Bt0 + (size_t)(bn * 128 + r) * CC + hh * 16;
    const bf16* pb1 = Bt1 + (size_t)(bn * 128 + r) * CC + hh * 16;
    const u32 st_off = (u32)(r * 80 + hh * 32);

    const int mw = (w & 1) * 64, nw = (w >> 1) * 32;

    float acc[4][2][2][4];
#pragma unroll
    for (int i = 0; i < 4; i++)
#pragma unroll
        for (int jj = 0; jj < 2; jj++)
#pragma unroll
            for (int j = 0; j < 2; j++)
#pragma unroll
                for (int q = 0; q < 4; q++) acc[i][jj][j][q] = 0.f;

    float4 af[4];
    uint4 vb0[2], vb1[2];

    auto load_chunk = [&](int c) {
        int k0 = c * 32;
#pragma unroll
        for (int q = 0; q < 4; q++) af[q] = *(const float4*)(pa + k0 + q * 4);
        vb0[0] = *(const uint4*)(pb0 + k0);
        vb0[1] = *(const uint4*)(pb0 + k0 + 8);
        vb1[0] = *(const uint4*)(pb1 + k0);
        vb1[1] = *(const uint4*)(pb1 + k0 + 8);
    };

    auto store_chunk = [&](int c) {
        u32 stg = sb + (u32)((c & 1) * 40960);
        u32 HI[8], LO[8];
#pragma unroll
        for (int q = 0; q < 4; q++) {
            __nv_bfloat162 h01 = __float22bfloat162_rn(make_float2(af[q].x, af[q].y));
            __nv_bfloat162 h23 = __float22bfloat162_rn(make_float2(af[q].z, af[q].w));
            float2 g01 = __bfloat1622float2(h01), g23 = __bfloat1622float2(h23);
            __nv_bfloat162 l01 = __float22bfloat162_rn(make_float2(af[q].x - g01.x, af[q].y - g01.y));
            __nv_bfloat162 l23 = __float22bfloat162_rn(make_float2(af[q].z - g23.x, af[q].w - g23.y));
            HI[2 * q] = bf2u(h01); HI[2 * q + 1] = bf2u(h23);
            LO[2 * q] = bf2u(l01); LO[2 * q + 1] = bf2u(l23);
        }
        sts128(stg + st_off,            make_uint4(HI[0], HI[1], HI[2], HI[3]));
        sts128(stg + st_off + 16,       make_uint4(HI[4], HI[5], HI[6], HI[7]));
        sts128(stg + 10240 + st_off,      make_uint4(LO[0], LO[1], LO[2], LO[3]));
        sts128(stg + 10240 + st_off + 16, make_uint4(LO[4], LO[5], LO[6], LO[7]));
        sts128(stg + 20480 + st_off,      vb0[0]);
        sts128(stg + 20480 + st_off + 16, vb0[1]);
        sts128(stg + 30720 + st_off,      vb1[0]);
        sts128(stg + 30720 + st_off + 16, vb1[1]);
    };

    auto compute_stage = [&](int s) {
        u32 stg = sb + (u32)(s * 40960);
#pragma unroll
        for (int ks = 0; ks < 2; ks++) {
            u32 ah[4][4], al[4][4], bh[2][4], bl[2][4];
            u32 acol = (u32)(ks * 32 + (l >> 4) * 16);
#pragma unroll
            for (int i = 0; i < 4; i++) {
                u32 arow = (u32)(mw + i * 16 + ((l >> 3) & 1) * 8 + (l & 7));
                ldsm4(ah[i][0], ah[i][1], ah[i][2], ah[i][3], stg + arow * 80 + acol);
                ldsm4(al[i][0], al[i][1], al[i][2], al[i][3], stg + 10240 + arow * 80 + acol);
            }
            u32 bcol = (u32)(ks * 32 + ((l >> 3) & 1) * 16);
#pragma unroll
            for (int jj = 0; jj < 2; jj++) {
                u32 nrow = (u32)(nw + jj * 16 + ((l >> 4) & 1) * 8 + (l & 7));
                ldsm4(bh[jj][0], bh[jj][1], bh[jj][2], bh[jj][3], stg + 20480 + nrow * 80 + bcol);
                ldsm4(bl[jj][0], bl[jj][1], bl[jj][2], bl[jj][3], stg + 30720 + nrow * 80 + bcol);
            }
#pragma unroll
            for (int i = 0; i < 4; i++)
#pragma unroll
                for (int jj = 0; jj < 2; jj++)
#pragma unroll
                    for (int j = 0; j < 2; j++) {
                        float* d = acc[i][jj][j];
                        mma16816(d, ah[i], &bh[jj][j * 2]);   // a0*b0
                        mma16816(d, ah[i], &bl[jj][j * 2]);   // a0*b1
                        mma16816(d, al[i], &bh[jj][j * 2]);   // a1*b0
                    }
        }
    };

    // ---- pipeline: 8 chunks of K=32, double-buffered, 1 barrier per chunk
    load_chunk(0);
    store_chunk(0);
    __syncthreads();
    load_chunk(1);
    for (int c = 0; c < 8; c++) {
        compute_stage(c & 1);
        if (c < 7) {
            store_chunk(c + 1);        // other stage; freed by barrier of iter c-1
            __syncthreads();
            if (c < 6) load_chunk(c + 2);
        }
    }

    // ---- epilogue: fragment layout d0,d1=(g, t*2..), d2,d3=(g+8, ...)
    {
        const int g = l >> 2, t = l & 3;
#pragma unroll
        for (int i = 0; i < 4; i++) {
            int gr0 = bm * 128 + mw + i * 16 + g;
            int gr1 = gr0 + 8;
            long row0 = SCATTER ? (long)src_row(gr0) : (long)gr0;
            long row1 = SCATTER ? (long)src_row(gr1) : (long)gr1;
#pragma unroll
            for (int jj = 0; jj < 2; jj++)
#pragma unroll
                for (int j = 0; j < 2; j++) {
                    int gc = bn * 128 + nw + jj * 16 + j * 8 + t * 2;
                    float b0 = bias[gc], b1 = bias[gc + 1];
                    float* d = acc[i][jj][j];
                    *(float2*)(C + (size_t)row0 * NT + gc) = make_float2(d[0] + b0, d[1] + b1);
                    *(float2*)(C + (size_t)row1 * NT + gc) = make_float2(d[2] + b0, d[3] + b1);
                }
        }
    }
}

// ---------------------------------------------------------------------------
// Attention kernel: one block per (window, head). 128 threads. (unchanged)
// ---------------------------------------------------------------------------
__global__ __launch_bounds__(128)
void attn_kernel(const float* __restrict__ Ek, const float* __restrict__ Ev,
                 const float* __restrict__ kbank, const float* __restrict__ vbank)
{
    const int bw  = blockIdx.x >> 3;
    const int h   = blockIdx.x & 7;
    const int tid = threadIdx.x;

    __shared__ float q[64][33];
    __shared__ float kf[48][33];
    __shared__ float vf[48][33];
    __shared__ float X[4096];
    float* kvb = X;
    float* eb  = X + 2048;
    float* sc  = X;                 // pitch 49

    const float* qkvbase = g_qkv + (size_t)(bw * 64) * NQKV + h * HDM;

    for (int idx = tid; idx < 2048; idx += 128) {
        int p = idx >> 5, d = idx & 31;
        q[p][d]  = qkvbase[p * NQKV + d];
        kvb[idx] = qkvbase[p * NQKV + 256 + d];
        eb[idx]  = Ek[idx];
    }
    for (int idx = tid; idx < 512; idx += 128) {
        int g = idx >> 5, d = idx & 31;
        kf[32 + g][d] = kbank[g * CC + h * HDM + d];
        vf[32 + g][d] = vbank[g * CC + h * HDM + d];
    }
    __syncthreads();

    {
        int lk0 = (tid >> 3) * 2;
        int d0  = (tid & 7) * 4;
        float a00 = 0.f, a01 = 0.f, a02 = 0.f, a03 = 0.f;
        float a10 = 0.f, a11 = 0.f, a12 = 0.f, a13 = 0.f;
#pragma unroll 4
        for (int p = 0; p < 64; p++) {
            float e0 = eb[p * 32 + lk0], e1 = eb[p * 32 + lk0 + 1];
            float b0 = kvb[p * 32 + d0 + 0], b1 = kvb[p * 32 + d0 + 1];
            float b2 = kvb[p * 32 + d0 + 2], b3 = kvb[p * 32 + d0 + 3];
            a00 += e0 * b0; a01 += e0 * b1; a02 += e0 * b2; a03 += e0 * b3;
            a10 += e1 * b0; a11 += e1 * b1; a12 += e1 * b2; a13 += e1 * b3;
        }
        kf[lk0][d0] = a00; kf[lk0][d0 + 1] = a01; kf[lk0][d0 + 2] = a02; kf[lk0][d0 + 3] = a03;
        kf[lk0 + 1][d0] = a10; kf[lk0 + 1][d0 + 1] = a11; kf[lk0 + 1][d0 + 2] = a12; kf[lk0 + 1][d0 + 3] = a13;
    }
    __syncthreads();

    for (int idx = tid; idx < 2048; idx += 128) {
        int p = idx >> 5, d = idx & 31;
        kvb[idx] = qkvbase[p * NQKV + 512 + d];
        eb[idx]  = Ev[idx];
    }
    __syncthreads();

    {
        int lk0 = (tid >> 3) * 2;
        int d0  = (tid & 7) * 4;
        float a00 = 0.f, a01 = 0.f, a02 = 0.f, a03 = 0.f;
        float a10 = 0.f, a11 = 0.f, a12 = 0.f, a13 = 0.f;
#pragma unroll 4
        for (int p = 0; p < 64; p++) {
            float e0 = eb[p * 32 + lk0], e1 = eb[p * 32 + lk0 + 1];
            float b0 = kvb[p * 32 + d0 + 0], b1 = kvb[p * 32 + d0 + 1];
            float b2 = kvb[p * 32 + d0 + 2], b3 = kvb[p * 32 + d0 + 3];
            a00 += e0 * b0; a01 += e0 * b1; a02 += e0 * b2; a03 += e0 * b3;
            a10 += e1 * b0; a11 += e1 * b1; a12 += e1 * b2; a13 += e1 * b3;
        }
        vf[lk0][d0] = a00; vf[lk0][d0 + 1] = a01; vf[lk0][d0 + 2] = a02; vf[lk0][d0 + 3] = a03;
        vf[lk0 + 1][d0] = a10; vf[lk0 + 1][d0 + 1] = a11; vf[lk0 + 1][d0 + 2] = a12; vf[lk0 + 1][d0 + 3] = a13;
    }
    __syncthreads();

    {
        int r0 = (tid >> 3) * 4;
        int c0 = (tid & 7) * 6;
        float acc[4][6];
#pragma unroll
        for (int i = 0; i < 4; i++)
#pragma unroll
            for (int j = 0; j < 6; j++) acc[i][j] = 0.f;
#pragma unroll 4
        for (int d = 0; d < 32; d++) {
            float a[4], b[6];
#pragma unroll
            for (int i = 0; i < 4; i++) a[i] = q[r0 + i][d];
#pragma unroll
            for (int j = 0; j < 6; j++) b[j] = kf[c0 + j][d];
#pragma unroll
            for (int i = 0; i < 4; i++)
#pragma unroll
                for (int j = 0; j < 6; j++) acc[i][j] += a[i] * b[j];
        }
        const float scale = 0.17677669529663687f;
#pragma unroll
        for (int i = 0; i < 4; i++)
#pragma unroll
            for (int j = 0; j < 6; j++)
                sc[(r0 + i) * 49 + c0 + j] = acc[i][j] * scale;
    }
    __syncthreads();

    if (tid < 64) {
        float m = -1e30f;
#pragma unroll
        for (int j = 0; j < 48; j++) m = fmaxf(m, sc[tid * 49 + j]);
        float s = 0.f;
#pragma unroll
        for (int j = 0; j < 48; j++) {
            float e = expf(sc[tid * 49 + j] - m);
            sc[tid * 49 + j] = e;
            s += e;
        }
        float inv = 1.f / s;
#pragma unroll
        for (int j = 0; j < 48; j++) sc[tid * 49 + j] *= inv;
    }
    __syncthreads();

    {
        int r0 = (tid >> 3) * 4;
        int c0 = (tid & 7) * 4;
        float acc[4][4];
#pragma unroll
        for (int i = 0; i < 4; i++)
#pragma unroll
            for (int j = 0; j < 4; j++) acc[i][j] = 0.f;
#pragma unroll 4
        for (int j = 0; j < 48; j++) {
            float a[4], b[4];
#pragma unroll
            for (int i = 0; i < 4; i++) a[i] = sc[(r0 + i) * 49 + j];
#pragma unroll
            for (int jj = 0; jj < 4; jj++) b[jj] = vf[j][c0 + jj];
#pragma unroll
            for (int i = 0; i < 4; i++)
#pragma unroll
                for (int jj = 0; jj < 4; jj++) acc[i][jj] += a[i] * b[jj];
        }
        float* ob = g_att + (size_t)(bw * 64) * CC + h * HDM;
#pragma unroll
        for (int i = 0; i < 4; i++) {
            float4 v;
            v.x = acc[i][0]; v.y = acc[i][1]; v.z = acc[i][2]; v.w = acc[i][3];
            *(float4*)(ob + (r0 + i) * CC + c0) = v;
        }
    }
}

// ---------------------------------------------------------------------------
extern "C" void kernel_launch(void* const* d_in, const int* in_sizes, int n_in,
                              void* d_out, int out_size)
{
    const float* x      = (const float*)d_in[0];
    const float* W_qkv  = (const float*)d_in[1];
    const float* b_qkv  = (const float*)d_in[2];
    const float* E_k    = (const float*)d_in[3];
    const float* E_v    = (const float*)d_in[4];
    const float* k_bank = (const float*)d_in[5];
    const float* v_bank = (const float*)d_in[6];
    const float* W_proj = (const float*)d_in[7];
    const float* b_proj = (const float*)d_in[8];
    float* out = (float*)d_out;

    float* qkv = nullptr;  float* att = nullptr;
    bf16 *wq0, *wq1, *wp0, *wp1;
    cudaGetSymbolAddress((void**)&qkv, g_qkv);
    cudaGetSymbolAddress((void**)&att, g_att);
    cudaGetSymbolAddress((void**)&wq0, g_wq0);
    cudaGetSymbolAddress((void**)&wq1, g_wq1);
    cudaGetSymbolAddress((void**)&wp0, g_wp0);
    cudaGetSymbolAddress((void**)&wp1, g_wp1);

    const int SMEM = 81920;
    cudaFuncSetAttribute(gemm_mma<NQKV, true, false>,
                         cudaFuncAttributeMaxDynamicSharedMemorySize, SMEM);
    cudaFuncSetAttribute(gemm_mma<CC, false, true>,
                         cudaFuncAttributeMaxDynamicSharedMemorySize, SMEM);

    // 0) weight transpose + bf16 split
    prep_w<<<768, 256>>>(W_qkv, W_proj);

    // 1) window-gather + QKV GEMM (HMMA): [65536,256] @ [256,768]
    gemm_mma<NQKV, true, false><<<dim3(NQKV / 128, MTOK / 128), 256, SMEM>>>(
        x, wq0, wq1, b_qkv, qkv);

    // 2) per (window, head) Linformer attention
    attn_kernel<<<BWIN * NHD, 128>>>(E_k, E_v, k_bank, v_bank);

    // 3) proj GEMM + window-reverse scatter (HMMA): [65536,256] @ [256,256]
    gemm_mma<CC, false, true><<<dim3(CC / 128, MTOK / 128), 256, SMEM>>>(
        att, wp0, wp1, b_proj, out);
}

// round 16
// speedup vs baseline: 1.8191x; 1.1160x over previous
#include <cuda_runtime.h>
#include <cuda_bf16.h>
#include <cstdint>
#include <cstring>

#define CC   256
#define NQKV 768
#define MTOK 65536
#define BWIN 1024
#define NHD  8
#define HDM  32

typedef unsigned long long u64;
typedef unsigned int u32;
typedef __nv_bfloat16 bf16;

// ---------------- scratch ----------------
__device__ float g_qkv[(size_t)MTOK * NQKV];     // window-ordered qkv (fp32)
__device__ bf16 g_a0[(size_t)MTOK * CC];         // x gathered+split hi
__device__ bf16 g_a1[(size_t)MTOK * CC];         // x gathered+split lo
__device__ bf16 g_att0[(size_t)MTOK * CC];       // attn out hi
__device__ bf16 g_att1[(size_t)MTOK * CC];       // attn out lo
__device__ bf16 g_wq0[NQKV * CC];                // W_qkv^T hi [n][k]
__device__ bf16 g_wq1[NQKV * CC];
__device__ bf16 g_wp0[CC * CC];                  // W_proj^T hi
__device__ bf16 g_wp1[CC * CC];

// window-ordered token index -> original token row
__device__ __forceinline__ int src_row(int wt) {
    int bw = wt >> 6, p = wt & 63;
    int b  = bw >> 6, w = bw & 63;
    int wy = w >> 3, wx = w & 7;
    int py = p >> 3, px = p & 7;
    return (b << 12) + ((wy * 8 + py) << 6) + (wx * 8 + px);
}

// ---------------- helpers ----------------
__device__ __forceinline__ u32 cvta_smem(const void* p) {
    u32 a;
    asm("{ .reg .u64 t; cvta.to.shared.u64 t, %1; cvt.u32.u64 %0, t; }" : "=r"(a) : "l"(p));
    return a;
}
__device__ __forceinline__ void cpasync16(u32 saddr, const void* gaddr) {
    asm volatile("cp.async.cg.shared.global [%0], [%1], 16;" :: "r"(saddr), "l"(gaddr));
}
__device__ __forceinline__ void cp_commit() {
    asm volatile("cp.async.commit_group;" ::: "memory");
}
template<int N> __device__ __forceinline__ void cp_wait() {
    asm volatile("cp.async.wait_group %0;" :: "n"(N) : "memory");
}
__device__ __forceinline__ void ldsm4(u32& r0, u32& r1, u32& r2, u32& r3, u32 addr) {
    asm volatile("ldmatrix.sync.aligned.m8n8.x4.shared.b16 {%0,%1,%2,%3}, [%4];"
                 : "=r"(r0), "=r"(r1), "=r"(r2), "=r"(r3) : "r"(addr));
}
__device__ __forceinline__ void mma16816(float* d, const u32* a, const u32* b) {
    asm volatile(
        "mma.sync.aligned.m16n8k16.row.col.f32.bf16.bf16.f32 "
        "{%0,%1,%2,%3}, {%4,%5,%6,%7}, {%8,%9}, {%0,%1,%2,%3};"
        : "+f"(d[0]), "+f"(d[1]), "+f"(d[2]), "+f"(d[3])
        : "r"(a[0]), "r"(a[1]), "r"(a[2]), "r"(a[3]), "r"(b[0]), "r"(b[1]));
}
__device__ __forceinline__ u32 bf2u(__nv_bfloat162 h) {
    u32 v; memcpy(&v, &h, 4); return v;
}

// ---------------------------------------------------------------------------
// split_x: window-gather + hi/lo bf16 split of the input activations
// ---------------------------------------------------------------------------
__global__ void split_x(const float* __restrict__ x) {
    int idx = blockIdx.x * 256 + threadIdx.x;   // 16384 blocks -> 4.19M float4
    int row = idx >> 6, c4 = (idx & 63) * 4;
    float4 v = *(const float4*)(x + (size_t)src_row(row) * CC + c4);
    __nv_bfloat162 h0 = __float22bfloat162_rn(make_float2(v.x, v.y));
    __nv_bfloat162 h1 = __float22bfloat162_rn(make_float2(v.z, v.w));
    float2 g0 = __bfloat1622float2(h0), g1 = __bfloat1622float2(h1);
    __nv_bfloat162 l0 = __float22bfloat162_rn(make_float2(v.x - g0.x, v.y - g0.y));
    __nv_bfloat162 l1 = __float22bfloat162_rn(make_float2(v.z - g1.x, v.w - g1.y));
    *(uint2*)(g_a0 + (size_t)row * CC + c4) = make_uint2(bf2u(h0), bf2u(h1));
    *(uint2*)(g_a1 + (size_t)row * CC + c4) = make_uint2(bf2u(l0), bf2u(l1));
}

// ---------------------------------------------------------------------------
// prep: transpose + hi/lo bf16 split of both weight matrices
// ---------------------------------------------------------------------------
__global__ void prep_w(const float* __restrict__ Wq, const float* __restrict__ Wp) {
    int i = blockIdx.x * 256 + threadIdx.x;
    {
        int n = i >> 8, k = i & 255;
        float f = Wq[k * NQKV + n];
        bf16 h = __float2bfloat16_rn(f);
        g_wq0[i] = h;
        g_wq1[i] = __float2bfloat16_rn(f - __bfloat162float(h));
    }
    if (i < CC * CC) {
        int n = i >> 8, k = i & 255;
        float f = Wp[k * CC + n];
        bf16 h = __float2bfloat16_rn(f);
        g_wp0[i] = h;
        g_wp1[i] = __float2bfloat16_rn(f - __bfloat162float(h));
    }
}

// ---------------------------------------------------------------------------
// HMMA GEMM, all-bf16 operands via cp.async: C[M,NT] = A[M,256]*W + bias
// 3-product split (a0b0 + a0b1 + a1b0). 128x128 tile, BK=32, 8 warps,
// warp tile 64x32, 2 CTAs/SM. smem stage (40960 B): A0 @0, A1 @10240,
// B0 @20480, B1 @30720; row pitch 80 B. 2 stages, cp.async pipeline.
// ---------------------------------------------------------------------------
template<int NT, bool SCATTER>
__global__ __launch_bounds__(256, 2)
void gemm_cp(const bf16* __restrict__ A0, const bf16* __restrict__ A1,
             const bf16* __restrict__ B0, const bf16* __restrict__ B1,
             const float* __restrict__ bias, float* __restrict__ C)
{
    extern __shared__ __align__(128) char dsm[];
    const u32 sb = cvta_smem(dsm);
    const int tid = threadIdx.x, w = tid >> 5, l = tid & 31;
    const int bn = blockIdx.x, bm = blockIdx.y;

    // cp.async coords: row r (0..127), half hh (32 B each of the 64 B chunk-row)
    const int r = tid >> 1, hh = tid & 1;
    const char* pa0 = (const char*)(A0 + (size_t)(bm * 128 + r) * CC) + hh * 32;
    const char* pa1 = (const char*)(A1 + (size_t)(bm * 128 + r) * CC) + hh * 32;
    const char* pb0 = (const char*)(B0 + (size_t)(bn * 128 + r) * CC) + hh * 32;
    const char* pb1 = (const char*)(B1 + (size_t)(bn * 128 + r) * CC) + hh * 32;
    const u32 so = (u32)(r * 80 + hh * 32);

    const int mw = (w & 1) * 64, nw = (w >> 1) * 32;

    float acc[4][2][2][4];
#pragma unroll
    for (int i = 0; i < 4; i++)
#pragma unroll
        for (int jj = 0; jj < 2; jj++)
#pragma unroll
            for (int j = 0; j < 2; j++)
#pragma unroll
                for (int q = 0; q < 4; q++) acc[i][jj][j][q] = 0.f;

    auto issue = [&](int c) {
        u32 stg = sb + (u32)((c & 1) * 40960);
        int kb = c * 64;                         // 32 bf16 = 64 B per chunk
        cpasync16(stg + so,              pa0 + kb);
        cpasync16(stg + so + 16,         pa0 + kb + 16);
        cpasync16(stg + 10240 + so,      pa1 + kb);
        cpasync16(stg + 10240 + so + 16, pa1 + kb + 16);
        cpasync16(stg + 20480 + so,      pb0 + kb);
        cpasync16(stg + 20480 + so + 16, pb0 + kb + 16);
        cpasync16(stg + 30720 + so,      pb1 + kb);
        cpasync16(stg + 30720 + so + 16, pb1 + kb + 16);
    };

    auto compute_stage = [&](int s) {
        u32 stg = sb + (u32)(s * 40960);
#pragma unroll
        for (int ks = 0; ks < 2; ks++) {
            u32 ah[4][4], al[4][4], bh[2][4], bl[2][4];
            u32 acol = (u32)(ks * 32 + (l >> 4) * 16);
#pragma unroll
            for (int i = 0; i < 4; i++) {
                u32 arow = (u32)(mw + i * 16 + ((l >> 3) & 1) * 8 + (l & 7));
                ldsm4(ah[i][0], ah[i][1], ah[i][2], ah[i][3], stg + arow * 80 + acol);
                ldsm4(al[i][0], al[i][1], al[i][2], al[i][3], stg + 10240 + arow * 80 + acol);
            }
            u32 bcol = (u32)(ks * 32 + ((l >> 3) & 1) * 16);
#pragma unroll
            for (int jj = 0; jj < 2; jj++) {
                u32 nrow = (u32)(nw + jj * 16 + ((l >> 4) & 1) * 8 + (l & 7));
                ldsm4(bh[jj][0], bh[jj][1], bh[jj][2], bh[jj][3], stg + 20480 + nrow * 80 + bcol);
                ldsm4(bl[jj][0], bl[jj][1], bl[jj][2], bl[jj][3], stg + 30720 + nrow * 80 + bcol);
            }
#pragma unroll
            for (int i = 0; i < 4; i++)
#pragma unroll
                for (int jj = 0; jj < 2; jj++)
#pragma unroll
                    for (int j = 0; j < 2; j++) {
                        float* d = acc[i][jj][j];
                        mma16816(d, ah[i], &bh[jj][j * 2]);   // a0*b0
                        mma16816(d, ah[i], &bl[jj][j * 2]);   // a0*b1
                        mma16816(d, al[i], &bh[jj][j * 2]);   // a1*b0
                    }
        }
    };

    // ---- pipeline: 8 chunks of K=32, 2 stages in flight
    issue(0); cp_commit();
    issue(1); cp_commit();
#pragma unroll
    for (int c = 0; c < 8; c++) {
        if (c < 7) cp_wait<1>(); else cp_wait<0>();
        __syncthreads();
        compute_stage(c & 1);
        if (c < 6) {
            __syncthreads();          // all warps done with this stage
            issue(c + 2);
            cp_commit();
        }
    }

    // ---- epilogue
    {
        const int g = l >> 2, t = l & 3;
#pragma unroll
        for (int i = 0; i < 4; i++) {
            int gr0 = bm * 128 + mw + i * 16 + g;
            int gr1 = gr0 + 8;
            long row0 = SCATTER ? (long)src_row(gr0) : (long)gr0;
            long row1 = SCATTER ? (long)src_row(gr1) : (long)gr1;
#pragma unroll
            for (int jj = 0; jj < 2; jj++)
#pragma unroll
                for (int j = 0; j < 2; j++) {
                    int gc = bn * 128 + nw + jj * 16 + j * 8 + t * 2;
                    float b0 = bias[gc], b1 = bias[gc + 1];
                    float* d = acc[i][jj][j];
                    *(float2*)(C + (size_t)row0 * NT + gc) = make_float2(d[0] + b0, d[1] + b1);
                    *(float2*)(C + (size_t)row1 * NT + gc) = make_float2(d[2] + b0, d[3] + b1);
                }
        }
    }
}

// ---------------------------------------------------------------------------
// Attention kernel: one block per (window, head). 128 threads.
// Output written as bf16 hi/lo split (feeds proj GEMM directly).
// ---------------------------------------------------------------------------
__global__ __launch_bounds__(128)
void attn_kernel(const float* __restrict__ Ek, const float* __restrict__ Ev,
                 const float* __restrict__ kbank, const float* __restrict__ vbank)
{
    const int bw  = blockIdx.x >> 3;
    const int h   = blockIdx.x & 7;
    const int tid = threadIdx.x;

    __shared__ float q[64][33];
    __shared__ float kf[48][33];
    __shared__ float vf[48][33];
    __shared__ float X[4096];
    float* kvb = X;
    float* eb  = X + 2048;
    float* sc  = X;                 // pitch 49

    const float* qkvbase = g_qkv + (size_t)(bw * 64) * NQKV + h * HDM;

    for (int idx = tid; idx < 2048; idx += 128) {
        int p = idx >> 5, d = idx & 31;
        q[p][d]  = qkvbase[p * NQKV + d];
        kvb[idx] = qkvbase[p * NQKV + 256 + d];
        eb[idx]  = Ek[idx];
    }
    for (int idx = tid; idx < 512; idx += 128) {
        int g = idx >> 5, d = idx & 31;
        kf[32 + g][d] = kbank[g * CC + h * HDM + d];
        vf[32 + g][d] = vbank[g * CC + h * HDM + d];
    }
    __syncthreads();

    {
        int lk0 = (tid >> 3) * 2;
        int d0  = (tid & 7) * 4;
        float a00 = 0.f, a01 = 0.f, a02 = 0.f, a03 = 0.f;
        float a10 = 0.f, a11 = 0.f, a12 = 0.f, a13 = 0.f;
#pragma unroll 4
        for (int p = 0; p < 64; p++) {
            float e0 = eb[p * 32 + lk0], e1 = eb[p * 32 + lk0 + 1];
            float b0 = kvb[p * 32 + d0 + 0], b1 = kvb[p * 32 + d0 + 1];
            float b2 = kvb[p * 32 + d0 + 2], b3 = kvb[p * 32 + d0 + 3];
            a00 += e0 * b0; a01 += e0 * b1; a02 += e0 * b2; a03 += e0 * b3;
            a10 += e1 * b0; a11 += e1 * b1; a12 += e1 * b2; a13 += e1 * b3;
        }
        kf[lk0][d0] = a00; kf[lk0][d0 + 1] = a01; kf[lk0][d0 + 2] = a02; kf[lk0][d0 + 3] = a03;
        kf[lk0 + 1][d0] = a10; kf[lk0 + 1][d0 + 1] = a11; kf[lk0 + 1][d0 + 2] = a12; kf[lk0 + 1][d0 + 3] = a13;
    }
    __syncthreads();

    for (int idx = tid; idx < 2048; idx += 128) {
        int p = idx >> 5, d = idx & 31;
        kvb[idx] = qkvbase[p * NQKV + 512 + d];
        eb[idx]  = Ev[idx];
    }
    __syncthreads();

    {
        int lk0 = (tid >> 3) * 2;
        int d0  = (tid & 7) * 4;
        float a00 = 0.f, a01 = 0.f, a02 = 0.f, a03 = 0.f;
        float a10 = 0.f, a11 = 0.f, a12 = 0.f, a13 = 0.f;
#pragma unroll 4
        for (int p = 0; p < 64; p++) {
            float e0 = eb[p * 32 + lk0], e1 = eb[p * 32 + lk0 + 1];
            float b0 = kvb[p * 32 + d0 + 0], b1 = kvb[p * 32 + d0 + 1];
            float b2 = kvb[p * 32 + d0 + 2], b3 = kvb[p * 32 + d0 + 3];
            a00 += e0 * b0; a01 += e0 * b1; a02 += e0 * b2; a03 += e0 * b3;
            a10 += e1 * b0; a11 += e1 * b1; a12 += e1 * b2; a13 += e1 * b3;
        }
        vf[lk0][d0] = a00; vf[lk0][d0 + 1] = a01; vf[lk0][d0 + 2] = a02; vf[lk0][d0 + 3] = a03;
        vf[lk0 + 1][d0] = a10; vf[lk0 + 1][d0 + 1] = a11; vf[lk0 + 1][d0 + 2] = a12; vf[lk0 + 1][d0 + 3] = a13;
    }
    __syncthreads();

    {
        int r0 = (tid >> 3) * 4;
        int c0 = (tid & 7) * 6;
        float acc[4][6];
#pragma unroll
        for (int i = 0; i < 4; i++)
#pragma unroll
            for (int j = 0; j < 6; j++) acc[i][j] = 0.f;
#pragma unroll 4
        for (int d = 0; d < 32; d++) {
            float a[4], b[6];
#pragma unroll
            for (int i = 0; i < 4; i++) a[i] = q[r0 + i][d];
#pragma unroll
            for (int j = 0; j < 6; j++) b[j] = kf[c0 + j][d];
#pragma unroll
            for (int i = 0; i < 4; i++)
#pragma unroll
                for (int j = 0; j < 6; j++) acc[i][j] += a[i] * b[j];
        }
        const float scale = 0.17677669529663687f;
#pragma unroll
        for (int i = 0; i < 4; i++)
#pragma unroll
            for (int j = 0; j < 6; j++)
                sc[(r0 + i) * 49 + c0 + j] = acc[i][j] * scale;
    }
    __syncthreads();

    if (tid < 64) {
        float m = -1e30f;
#pragma unroll
        for (int j = 0; j < 48; j++) m = fmaxf(m, sc[tid * 49 + j]);
        float s = 0.f;
#pragma unroll
        for (int j = 0; j < 48; j++) {
            float e = expf(sc[tid * 49 + j] - m);
            sc[tid * 49 + j] = e;
            s += e;
        }
        float inv = 1.f / s;
#pragma unroll
        for (int j = 0; j < 48; j++) sc[tid * 49 + j] *= inv;
    }
    __syncthreads();

    {
        int r0 = (tid >> 3) * 4;
        int c0 = (tid & 7) * 4;
        float acc[4][4];
#pragma unroll
        for (int i = 0; i < 4; i++)
#pragma unroll
            for (int j = 0; j < 4; j++) acc[i][j] = 0.f;
#pragma unroll 4
        for (int j = 0; j < 48; j++) {
            float a[4], b[4];
#pragma unroll
            for (int i = 0; i < 4; i++) a[i] = sc[(r0 + i) * 49 + j];
#pragma unroll
            for (int jj = 0; jj < 4; jj++) b[jj] = vf[j][c0 + jj];
#pragma unroll
            for (int i = 0; i < 4; i++)
#pragma unroll
                for (int jj = 0; jj < 4; jj++) acc[i][jj] += a[i] * b[jj];
        }
        bf16* o0 = g_att0 + (size_t)(bw * 64) * CC + h * HDM;
        bf16* o1 = g_att1 + (size_t)(bw * 64) * CC + h * HDM;
#pragma unroll
        for (int i = 0; i < 4; i++) {
            __nv_bfloat162 h01 = __float22bfloat162_rn(make_float2(acc[i][0], acc[i][1]));
            __nv_bfloat162 h23 = __float22bfloat162_rn(make_float2(acc[i][2], acc[i][3]));
            float2 g01 = __bfloat1622float2(h01), g23 = __bfloat1622float2(h23);
            __nv_bfloat162 l01 = __float22bfloat162_rn(make_float2(acc[i][0] - g01.x, acc[i][1] - g01.y));
            __nv_bfloat162 l23 = __float22bfloat162_rn(make_float2(acc[i][2] - g23.x, acc[i][3] - g23.y));
            *(uint2*)(o0 + (r0 + i) * CC + c0) = make_uint2(bf2u(h01), bf2u(h23));
            *(uint2*)(o1 + (r0 + i) * CC + c0) = make_uint2(bf2u(l01), bf2u(l23));
        }
    }
}

// ---------------------------------------------------------------------------
extern "C" void kernel_launch(void* const* d_in, const int* in_sizes, int n_in,
                              void* d_out, int out_size)
{
    const float* x      = (const float*)d_in[0];
    const float* W_qkv  = (const float*)d_in[1];
    const float* b_qkv  = (const float*)d_in[2];
    const float* E_k    = (const float*)d_in[3];
    const float* E_v    = (const float*)d_in[4];
    const float* k_bank = (const float*)d_in[5];
    const float* v_bank = (const float*)d_in[6];
    const float* W_proj = (const float*)d_in[7];
    const float* b_proj = (const float*)d_in[8];
    float* out = (float*)d_out;

    float* qkv = nullptr;
    bf16 *a0, *a1, *at0, *at1, *wq0, *wq1, *wp0, *wp1;
    cudaGetSymbolAddress((void**)&qkv, g_qkv);
    cudaGetSymbolAddress((void**)&a0,  g_a0);
    cudaGetSymbolAddress((void**)&a1,  g_a1);
    cudaGetSymbolAddress((void**)&at0, g_att0);
    cudaGetSymbolAddress((void**)&at1, g_att1);
    cudaGetSymbolAddress((void**)&wq0, g_wq0);
    cudaGetSymbolAddress((void**)&wq1, g_wq1);
    cudaGetSymbolAddress((void**)&wp0, g_wp0);
    cudaGetSymbolAddress((void**)&wp1, g_wp1);

    const int SMEM = 81920;
    cudaFuncSetAttribute(gemm_cp<NQKV, false>,
                         cudaFuncAttributeMaxDynamicSharedMemorySize, SMEM);
    cudaFuncSetAttribute(gemm_cp<CC, true>,
                         cudaFuncAttributeMaxDynamicSharedMemorySize, SMEM);

    // 0) weight prep + activation gather/split
    prep_w<<<768, 256>>>(W_qkv, W_proj);
    split_x<<<16384, 256>>>(x);

    // 1) QKV GEMM (HMMA, cp.async): [65536,256] @ [256,768]
    gemm_cp<NQKV, false><<<dim3(NQKV / 128, MTOK / 128), 256, SMEM>>>(
        a0, a1, wq0, wq1, b_qkv, qkv);

    // 2) per (window, head) Linformer attention (writes bf16 hi/lo)
    attn_kernel<<<BWIN * NHD, 128>>>(E_k, E_v, k_bank, v_bank);

    // 3) proj GEMM + window-reverse scatter: [65536,256] @ [256,256]
    gemm_cp<CC, true><<<dim3(CC / 128, MTOK / 128), 256, SMEM>>>(
        at0, at1, wp0, wp1, b_proj, out);
}